// round 9
// baseline (speedup 1.0000x reference)
#include <cuda_runtime.h>
#include <cuda_fp16.h>

#define NN 100000
#define EE 1600000
#define SCAN_BLK 1024
#define SCAN_NB ((NN + SCAN_BLK - 1) / SCAN_BLK)   // 98

// ---------------- scratch (no allocations allowed) ----------------
__device__ int    g_is64;
__device__ int    g_deg[NN];
__device__ int    g_off[NN];
__device__ int    g_cur[NN];
__device__ int    g_csr[EE];
__device__ int    g_part[128];
__device__ int    g_partoff[128];
__device__ float  g_h[NN * 128];     // agg output (GEMM-A input)
__device__ float  g_t[NN * 128];     // MLP mid
__device__ float  g_x[NN * 128];     // final layer fp32 out
__device__ __half g_xh[NN * 128];    // fp16 activations (gather source)

__device__ __forceinline__ float* gbuf(int i) {
    return (i == 0) ? g_h : (i == 1) ? g_t : g_x;
}

// ---------------- dtype detection (int64 vs silently-downcast int32) ----------------
__global__ void k_detect(const long long* __restrict__ e64) {
    __shared__ int bad;
    if (threadIdx.x == 0) bad = 0;
    __syncthreads();
    for (int i = threadIdx.x; i < 4096; i += blockDim.x) {
        long long v = e64[i];
        if (v < 0 || v >= NN) bad = 1;
    }
    __syncthreads();
    if (threadIdx.x == 0) g_is64 = bad ? 0 : 1;
}

// ---------------- CSR build ----------------
__global__ void k_zero_deg() {
    int i = blockIdx.x * blockDim.x + threadIdx.x;
    if (i < NN) g_deg[i] = 0;
}

__device__ __forceinline__ int edge_at(const void* ei, int idx) {
    if (g_is64) return (int)((const long long*)ei)[idx];
    return ((const int*)ei)[idx];
}

__global__ void k_hist(const void* __restrict__ ei) {
    int e = blockIdx.x * blockDim.x + threadIdx.x;
    if (e < EE) {
        int d = edge_at(ei, EE + e);
        if ((unsigned)d < (unsigned)NN) atomicAdd(&g_deg[d], 1);
    }
}

__global__ void k_block_sums() {
    int i = blockIdx.x * SCAN_BLK + threadIdx.x;
    int v = (i < NN) ? g_deg[i] : 0;
    #pragma unroll
    for (int o = 16; o > 0; o >>= 1) v += __shfl_down_sync(0xffffffffu, v, o);
    __shared__ int ws[32];
    int wid = threadIdx.x >> 5, lane = threadIdx.x & 31;
    if (lane == 0) ws[wid] = v;
    __syncthreads();
    if (wid == 0) {
        int s = ws[lane];
        #pragma unroll
        for (int o = 16; o > 0; o >>= 1) s += __shfl_down_sync(0xffffffffu, s, o);
        if (lane == 0) g_part[blockIdx.x] = s;
    }
}

__global__ void k_scan_parts() {
    __shared__ int sm[128];
    int t = threadIdx.x;
    int v = (t < SCAN_NB) ? g_part[t] : 0;
    sm[t] = v;
    __syncthreads();
    #pragma unroll
    for (int o = 1; o < 128; o <<= 1) {
        int u = (t >= o) ? sm[t - o] : 0;
        __syncthreads();
        sm[t] += u;
        __syncthreads();
    }
    g_partoff[t] = sm[t] - v;   // exclusive
}

__global__ void k_scan_final() {
    int i = blockIdx.x * SCAN_BLK + threadIdx.x;
    int v = (i < NN) ? g_deg[i] : 0;
    int wid = threadIdx.x >> 5, lane = threadIdx.x & 31;
    int incl = v;
    #pragma unroll
    for (int o = 1; o < 32; o <<= 1) {
        int u = __shfl_up_sync(0xffffffffu, incl, o);
        if (lane >= o) incl += u;
    }
    __shared__ int ws[32];
    if (lane == 31) ws[wid] = incl;
    __syncthreads();
    if (wid == 0) {
        int s = ws[lane];
        #pragma unroll
        for (int o = 1; o < 32; o <<= 1) {
            int u = __shfl_up_sync(0xffffffffu, s, o);
            if (lane >= o) s += u;
        }
        ws[lane] = s - ws[lane];
    }
    __syncthreads();
    if (i < NN) {
        int e = incl - v + ws[wid] + g_partoff[blockIdx.x];
        g_off[i] = e;
        g_cur[i] = e;
    }
}

__global__ void k_fill(const void* __restrict__ ei) {
    int e = blockIdx.x * blockDim.x + threadIdx.x;
    if (e < EE) {
        int d = edge_at(ei, EE + e);
        int s = edge_at(ei, e);
        if ((unsigned)d < (unsigned)NN && (unsigned)s < (unsigned)NN) {
            int p = atomicAdd(&g_cur[d], 1);
            if ((unsigned)p < (unsigned)EE) g_csr[p] = s;
        }
    }
}

// ---------------- x (fp32) -> g_xh (fp16) for layer-1 gather ----------------
__global__ void k_x2h(const float* __restrict__ x) {
    int i = blockIdx.x * blockDim.x + threadIdx.x;
    if (i < NN * 32) {
        float2 f = ((const float2*)x)[i];
        ((__half2*)g_xh)[i] = __floats2half2_rn(f.x, f.y);
    }
}

// ---------------- aggregation from fp16: g_h = (1+eps)*xh_i + sum xh_j (fp32 acc) ----
template <int F>
__global__ void k_aggh(const float* __restrict__ epsp) {
    int gw = (blockIdx.x * blockDim.x + threadIdx.x) >> 5;
    if (gw >= NN) return;
    int lane = threadIdx.x & 31;
    float scale = 1.0f + __ldg(epsp);
    int start = g_off[gw];
    int end = g_cur[gw];
    if (start < 0) start = 0;
    if (end > EE) end = EE;
    if (end < start) end = start;

    if (F == 128) {
        const uint2* xh = (const uint2*)g_xh;   // 4 halfs / uint2; row = 32 uint2
        uint2 sv = xh[gw * 32 + lane];
        float2 s0 = __half22float2(*reinterpret_cast<__half2*>(&sv.x));
        float2 s1 = __half22float2(*reinterpret_cast<__half2*>(&sv.y));
        float4 acc = make_float4(s0.x * scale, s0.y * scale, s1.x * scale, s1.y * scale);
        for (int j = start; j < end; j++) {
            uint2 v = xh[g_csr[j] * 32 + lane];
            float2 f0 = __half22float2(*reinterpret_cast<__half2*>(&v.x));
            float2 f1 = __half22float2(*reinterpret_cast<__half2*>(&v.y));
            acc.x += f0.x; acc.y += f0.y; acc.z += f1.x; acc.w += f1.y;
        }
        ((float4*)g_h)[gw * 32 + lane] = acc;
    } else {                                    // F == 64: row = 32 half2
        const __half2* xh = (const __half2*)g_xh;
        float2 s = __half22float2(xh[gw * 32 + lane]);
        float2 acc = make_float2(s.x * scale, s.y * scale);
        for (int j = start; j < end; j++) {
            float2 f = __half22float2(xh[g_csr[j] * 32 + lane]);
            acc.x += f.x; acc.y += f.y;
        }
        ((float2*)g_h)[gw * 32 + lane] = acc;
    }
}

// ---------------- SGEMM v2: double-buffered, warp-tiled, f32x2 ----------------
// Y = relu(X @ W + b); X = gbuf(SRC) (M=NN rows, K cols), W (K x HOUT).
// 512 threads, BM=128, TM=4, TN=HOUT/16. Warp tile = 8 tx x 4 ty (lower unique
// smem bytes per warp). Double-buffered smem, 1 barrier per k-step.
// HALF_OUT: write __half to g_xh instead of float to gbuf(DST).
template <int K, int HOUT, int SRC, int DST, bool HALF_OUT>
__global__ __launch_bounds__(512) void k_gemm(const float* __restrict__ W,
                                              const float* __restrict__ B) {
    const int BM = 128, BN = HOUT, BK = 16;
    const int TM = 4, TN = BN / 16, TN2 = TN / 2;   // TN 8|4, TN2 4|2
    const int NK = K / BK;
    __shared__ __align__(16) float As[2][BK][BM];
    __shared__ __align__(16) float Bs[2][BK][BN];

    const float* X = gbuf(SRC);

    int tid = threadIdx.x;
    int row0 = blockIdx.x * BM;
    int warp = tid >> 5, lane = tid & 31;
    int tx = (lane & 7) | ((warp & 1) << 3);        // 0..15
    int ty = (lane >> 3) | ((warp >> 1) << 2);      // 0..31

    // A-tile loader mapping: 512 float4 elems, 1 per thread
    int ar = tid >> 2;                              // 0..127
    int akv = tid & 3;                              // 0..3
    int arow_base = row0 + ar;
    // B-tile loader mapping
    int brk, bc4;
    if (BN == 128) { brk = tid >> 5; bc4 = tid & 31; }   // 512 float4
    else           { brk = tid >> 4; bc4 = tid & 15; }   // 256 float4 (tid<256)

    float4 pa, pb;
    // prefetch k0 = 0
    {
        int arow = arow_base; if (arow >= NN) arow = NN - 1;
        pa = *(const float4*)&X[arow * K + akv * 4];
        if (BN == 128 || tid < 256)
            pb = *(const float4*)&W[brk * HOUT + bc4 * 4];
    }
    // store tile 0
    {
        As[0][akv * 4 + 0][ar] = pa.x;
        As[0][akv * 4 + 1][ar] = pa.y;
        As[0][akv * 4 + 2][ar] = pa.z;
        As[0][akv * 4 + 3][ar] = pa.w;
        if (BN == 128 || tid < 256)
            *(float4*)&Bs[0][brk][bc4 * 4] = pb;
    }
    __syncthreads();

    unsigned long long acc2[TM][TN2];
    #pragma unroll
    for (int i = 0; i < TM; i++)
        #pragma unroll
        for (int j = 0; j < TN2; j++) acc2[i][j] = 0ull;

    for (int it = 0; it < NK; it++) {
        int cur = it & 1;
        // prefetch next tile into registers (overlaps with compute)
        if (it + 1 < NK) {
            int k0 = (it + 1) * BK;
            int arow = arow_base; if (arow >= NN) arow = NN - 1;
            pa = *(const float4*)&X[arow * K + k0 + akv * 4];
            if (BN == 128 || tid < 256)
                pb = *(const float4*)&W[(k0 + brk) * HOUT + bc4 * 4];
        }
        // compute on current buffer
        #pragma unroll
        for (int kk = 0; kk < BK; kk++) {
            float4 a4 = *(const float4*)&As[cur][kk][ty * 4];
            unsigned long long a2[TM];
            asm("mov.b64 %0, {%1, %1};" : "=l"(a2[0]) : "f"(a4.x));
            asm("mov.b64 %0, {%1, %1};" : "=l"(a2[1]) : "f"(a4.y));
            asm("mov.b64 %0, {%1, %1};" : "=l"(a2[2]) : "f"(a4.z));
            asm("mov.b64 %0, {%1, %1};" : "=l"(a2[3]) : "f"(a4.w));
            unsigned long long b2[TN2];
            const unsigned long long* bp =
                (const unsigned long long*)&Bs[cur][kk][tx * TN];
            #pragma unroll
            for (int j = 0; j < TN2; j++) b2[j] = bp[j];
            #pragma unroll
            for (int i = 0; i < TM; i++)
                #pragma unroll
                for (int j = 0; j < TN2; j++)
                    asm("fma.rn.f32x2 %0, %1, %2, %0;"
                        : "+l"(acc2[i][j]) : "l"(a2[i]), "l"(b2[j]));
        }
        // stage next tile
        if (it + 1 < NK) {
            int nxt = 1 - cur;
            As[nxt][akv * 4 + 0][ar] = pa.x;
            As[nxt][akv * 4 + 1][ar] = pa.y;
            As[nxt][akv * 4 + 2][ar] = pa.z;
            As[nxt][akv * 4 + 3][ar] = pa.w;
            if (BN == 128 || tid < 256)
                *(float4*)&Bs[nxt][brk][bc4 * 4] = pb;
        }
        __syncthreads();
    }

    // epilogue: bias + relu, store float or half
    float bs[TN];
    #pragma unroll
    for (int j = 0; j < TN; j++) bs[j] = B[tx * TN + j];

    #pragma unroll
    for (int i = 0; i < TM; i++) {
        int r = row0 + ty * 4 + i;
        if (r < NN) {
            float v[TN];
            #pragma unroll
            for (int j = 0; j < TN2; j++)
                asm("mov.b64 {%0, %1}, %2;"
                    : "=f"(v[2 * j]), "=f"(v[2 * j + 1]) : "l"(acc2[i][j]));
            #pragma unroll
            for (int j = 0; j < TN; j++) v[j] = fmaxf(v[j] + bs[j], 0.0f);
            if (HALF_OUT) {
                #pragma unroll
                for (int j = 0; j < TN; j += 2)
                    *(__half2*)&g_xh[r * HOUT + tx * TN + j] =
                        __floats2half2_rn(v[j], v[j + 1]);
            } else {
                float* Y = gbuf(DST);
                #pragma unroll
                for (int j = 0; j < TN; j += 4) {
                    float4 o = make_float4(v[j], v[j + 1], v[j + 2], v[j + 3]);
                    *(float4*)&Y[r * HOUT + tx * TN + j] = o;
                }
            }
        }
    }
}

// ---------------- final FC (N,64)@(64,8)+b and emb copy ----------------
template <int SRC>
__global__ void k_fc(const float* __restrict__ W,
                     const float* __restrict__ B,
                     float* __restrict__ out,
                     float* __restrict__ emb) {
    int gw = (blockIdx.x * blockDim.x + threadIdx.x) >> 5;
    if (gw >= NN) return;
    int lane = threadIdx.x & 31;
    const float* X = gbuf(SRC);
    float v0 = X[gw * 64 + lane];
    float v1 = X[gw * 64 + 32 + lane];
    emb[gw * 64 + lane] = v0;
    emb[gw * 64 + 32 + lane] = v1;
    #pragma unroll
    for (int j = 0; j < 8; j++) {
        float p = v0 * W[lane * 8 + j] + v1 * W[(lane + 32) * 8 + j];
        #pragma unroll
        for (int o = 16; o > 0; o >>= 1)
            p += __shfl_down_sync(0xffffffffu, p, o);
        if (lane == 0) out[gw * 8 + j] = p + B[j];
    }
}

// ---------------- launch ----------------
extern "C" void kernel_launch(void* const* d_in, const int* in_sizes, int n_in,
                              void* d_out, int out_size) {
    const float* x    = (const float*)d_in[0];
    const void*  ei   = d_in[1];
    const float* eps1 = (const float*)d_in[2];
    const float* eps2 = (const float*)d_in[3];
    const float* eps3 = (const float*)d_in[4];
    const float* W1a  = (const float*)d_in[5];
    const float* b1a  = (const float*)d_in[6];
    const float* W1b  = (const float*)d_in[7];
    const float* b1b  = (const float*)d_in[8];
    const float* W2a  = (const float*)d_in[9];
    const float* b2a  = (const float*)d_in[10];
    const float* W2b  = (const float*)d_in[11];
    const float* b2b  = (const float*)d_in[12];
    const float* W3a  = (const float*)d_in[13];
    const float* b3a  = (const float*)d_in[14];
    const float* W3b  = (const float*)d_in[15];
    const float* b3b  = (const float*)d_in[16];
    const float* Wfc  = (const float*)d_in[17];
    const float* bfc  = (const float*)d_in[18];

    float* out = (float*)d_out;             // (N, 8)
    float* emb = out + NN * 8;              // (N, 64)

    // CSR build
    k_detect<<<1, 1024>>>((const long long*)ei);
    k_zero_deg<<<(NN + 255) / 256, 256>>>();
    k_hist<<<(EE + 255) / 256, 256>>>(ei);
    k_block_sums<<<SCAN_NB, SCAN_BLK>>>();
    k_scan_parts<<<1, 128>>>();
    k_scan_final<<<SCAN_NB, SCAN_BLK>>>();
    k_fill<<<(EE + 255) / 256, 256>>>(ei);

    // input to fp16
    k_x2h<<<(NN * 32 + 255) / 256, 256>>>(x);

    const int aggBlocks = (NN * 32 + 255) / 256;
    const int gemmBlocks = (NN + 127) / 128;

    // Layer 1: 64 -> 128 -> 128 (half out)
    k_aggh<64><<<aggBlocks, 256>>>(eps1);
    k_gemm<64, 128, 0, 1, false><<<gemmBlocks, 512>>>(W1a, b1a);
    k_gemm<128, 128, 1, 2, true><<<gemmBlocks, 512>>>(W1b, b1b);

    // Layer 2: 128 -> 128 -> 128 (half out)
    k_aggh<128><<<aggBlocks, 256>>>(eps2);
    k_gemm<128, 128, 0, 1, false><<<gemmBlocks, 512>>>(W2a, b2a);
    k_gemm<128, 128, 1, 2, true><<<gemmBlocks, 512>>>(W2b, b2b);

    // Layer 3: 128 -> 64 -> 64 (float out to g_x)
    k_aggh<128><<<aggBlocks, 256>>>(eps3);
    k_gemm<128, 64, 0, 1, false><<<gemmBlocks, 512>>>(W3a, b3a);
    k_gemm<64, 64, 1, 2, false><<<gemmBlocks, 512>>>(W3b, b3b);

    // FC + emb
    k_fc<2><<<aggBlocks, 256>>>(Wfc, bfc, out, emb);
}

// round 10
// speedup vs baseline: 1.3220x; 1.3220x over previous
#include <cuda_runtime.h>
#include <cuda_fp16.h>

#define NN 100000
#define EE 1600000
#define SCAN_BLK 1024
#define SCAN_NB ((NN + SCAN_BLK - 1) / SCAN_BLK)   // 98

// ---------------- scratch (no allocations allowed) ----------------
__device__ int    g_is64;
__device__ int    g_deg[NN];
__device__ int    g_off[NN];
__device__ int    g_cur[NN];
__device__ int    g_csr[EE];
__device__ int    g_part[128];
__device__ int    g_partoff[128];
__device__ float  g_h[NN * 128];     // agg output (GEMM-A input)
__device__ float  g_t[NN * 128];     // MLP mid
__device__ float  g_x[NN * 128];     // final layer fp32 out
__device__ __half g_xh[NN * 128];    // fp16 activations (gather source)

__device__ __forceinline__ float* gbuf(int i) {
    return (i == 0) ? g_h : (i == 1) ? g_t : g_x;
}

// ---------------- dtype detection (int64 vs silently-downcast int32) ----------------
__global__ void k_detect(const long long* __restrict__ e64) {
    __shared__ int bad;
    if (threadIdx.x == 0) bad = 0;
    __syncthreads();
    for (int i = threadIdx.x; i < 4096; i += blockDim.x) {
        long long v = e64[i];
        if (v < 0 || v >= NN) bad = 1;
    }
    __syncthreads();
    if (threadIdx.x == 0) g_is64 = bad ? 0 : 1;
}

// ---------------- CSR build ----------------
__global__ void k_zero_deg() {
    int i = blockIdx.x * blockDim.x + threadIdx.x;
    if (i < NN) g_deg[i] = 0;
}

__device__ __forceinline__ int edge_at(const void* ei, int idx) {
    if (g_is64) return (int)((const long long*)ei)[idx];
    return ((const int*)ei)[idx];
}

__global__ void k_hist(const void* __restrict__ ei) {
    int e = blockIdx.x * blockDim.x + threadIdx.x;
    if (e < EE) {
        int d = edge_at(ei, EE + e);
        if ((unsigned)d < (unsigned)NN) atomicAdd(&g_deg[d], 1);
    }
}

__global__ void k_block_sums() {
    int i = blockIdx.x * SCAN_BLK + threadIdx.x;
    int v = (i < NN) ? g_deg[i] : 0;
    #pragma unroll
    for (int o = 16; o > 0; o >>= 1) v += __shfl_down_sync(0xffffffffu, v, o);
    __shared__ int ws[32];
    int wid = threadIdx.x >> 5, lane = threadIdx.x & 31;
    if (lane == 0) ws[wid] = v;
    __syncthreads();
    if (wid == 0) {
        int s = ws[lane];
        #pragma unroll
        for (int o = 16; o > 0; o >>= 1) s += __shfl_down_sync(0xffffffffu, s, o);
        if (lane == 0) g_part[blockIdx.x] = s;
    }
}

__global__ void k_scan_parts() {
    __shared__ int sm[128];
    int t = threadIdx.x;
    int v = (t < SCAN_NB) ? g_part[t] : 0;
    sm[t] = v;
    __syncthreads();
    #pragma unroll
    for (int o = 1; o < 128; o <<= 1) {
        int u = (t >= o) ? sm[t - o] : 0;
        __syncthreads();
        sm[t] += u;
        __syncthreads();
    }
    g_partoff[t] = sm[t] - v;   // exclusive
}

__global__ void k_scan_final() {
    int i = blockIdx.x * SCAN_BLK + threadIdx.x;
    int v = (i < NN) ? g_deg[i] : 0;
    int wid = threadIdx.x >> 5, lane = threadIdx.x & 31;
    int incl = v;
    #pragma unroll
    for (int o = 1; o < 32; o <<= 1) {
        int u = __shfl_up_sync(0xffffffffu, incl, o);
        if (lane >= o) incl += u;
    }
    __shared__ int ws[32];
    if (lane == 31) ws[wid] = incl;
    __syncthreads();
    if (wid == 0) {
        int s = ws[lane];
        #pragma unroll
        for (int o = 1; o < 32; o <<= 1) {
            int u = __shfl_up_sync(0xffffffffu, s, o);
            if (lane >= o) s += u;
        }
        ws[lane] = s - ws[lane];
    }
    __syncthreads();
    if (i < NN) {
        int e = incl - v + ws[wid] + g_partoff[blockIdx.x];
        g_off[i] = e;
        g_cur[i] = e;
    }
}

__global__ void k_fill(const void* __restrict__ ei) {
    int e = blockIdx.x * blockDim.x + threadIdx.x;
    if (e < EE) {
        int d = edge_at(ei, EE + e);
        int s = edge_at(ei, e);
        if ((unsigned)d < (unsigned)NN && (unsigned)s < (unsigned)NN) {
            int p = atomicAdd(&g_cur[d], 1);
            if ((unsigned)p < (unsigned)EE) g_csr[p] = s;
        }
    }
}

// ---------------- x (fp32) -> g_xh (fp16) for layer-1 gather ----------------
__global__ void k_x2h(const float* __restrict__ x) {
    int i = blockIdx.x * blockDim.x + threadIdx.x;
    if (i < NN * 32) {
        float2 f = ((const float2*)x)[i];
        ((__half2*)g_xh)[i] = __floats2half2_rn(f.x, f.y);
    }
}

// ---------------- aggregation from fp16: g_h = (1+eps)*xh_i + sum xh_j (fp32 acc) ----
template <int F>
__global__ void k_aggh(const float* __restrict__ epsp) {
    int gw = (blockIdx.x * blockDim.x + threadIdx.x) >> 5;
    if (gw >= NN) return;
    int lane = threadIdx.x & 31;
    float scale = 1.0f + __ldg(epsp);
    int start = g_off[gw];
    int end = g_cur[gw];
    if (start < 0) start = 0;
    if (end > EE) end = EE;
    if (end < start) end = start;

    if (F == 128) {
        const uint2* xh = (const uint2*)g_xh;   // 4 halfs / uint2; row = 32 uint2
        uint2 sv = xh[gw * 32 + lane];
        float2 s0 = __half22float2(*reinterpret_cast<__half2*>(&sv.x));
        float2 s1 = __half22float2(*reinterpret_cast<__half2*>(&sv.y));
        float4 acc = make_float4(s0.x * scale, s0.y * scale, s1.x * scale, s1.y * scale);
        for (int j = start; j < end; j++) {
            uint2 v = xh[g_csr[j] * 32 + lane];
            float2 f0 = __half22float2(*reinterpret_cast<__half2*>(&v.x));
            float2 f1 = __half22float2(*reinterpret_cast<__half2*>(&v.y));
            acc.x += f0.x; acc.y += f0.y; acc.z += f1.x; acc.w += f1.y;
        }
        ((float4*)g_h)[gw * 32 + lane] = acc;
    } else {                                    // F == 64: row = 32 half2
        const __half2* xh = (const __half2*)g_xh;
        float2 s = __half22float2(xh[gw * 32 + lane]);
        float2 acc = make_float2(s.x * scale, s.y * scale);
        for (int j = start; j < end; j++) {
            float2 f = __half22float2(xh[g_csr[j] * 32 + lane]);
            acc.x += f.x; acc.y += f.y;
        }
        ((float2*)g_h)[gw * 32 + lane] = acc;
    }
}

// ---------------- SGEMM (R8 version) + optional half output ----------------
// gbuf(DST) or g_xh = relu(gbuf(SRC) @ W + b)
// BM=128, BN=HOUT (128 or 64), BK=16, 256 threads, TM=8 x TN=(BN/16) per thread.
// Packed fma.rn.f32x2 accumulators (bit-identical IEEE fp32 per half).
template <int K, int HOUT, int SRC, int DST, bool HALF_OUT>
__global__ __launch_bounds__(256) void k_gemm(const float* __restrict__ W,
                                              const float* __restrict__ B) {
    const int BM = 128, BN = HOUT, BK = 16;
    const int TM = 8, TN = BN / 16;          // 8 or 4
    const int TN2 = TN / 2;                  // 4 or 2
    __shared__ __align__(16) float As[BK][BM];
    __shared__ __align__(16) float Bs[BK][BN];

    const float* X = gbuf(SRC);

    int tid = threadIdx.x;
    int row0 = blockIdx.x * BM;
    int tx = tid & 15;          // 0..15 -> TN cols each
    int ty = tid >> 4;          // 0..15 -> TM rows each

    unsigned long long acc2[TM][TN2];        // packed {f32,f32}; 0ull == {0.f,0.f}
    #pragma unroll
    for (int i = 0; i < TM; i++)
        #pragma unroll
        for (int j = 0; j < TN2; j++) acc2[i][j] = 0ull;

    for (int k0 = 0; k0 < K; k0 += BK) {
        // load A tile: BM x BK = 512 float4, 2 per thread; clamp row (safe, store guarded)
        #pragma unroll
        for (int l = 0; l < 2; l++) {
            int f = tid + l * 256;          // 0..511
            int r = f >> 2;                 // 0..127
            int kv = f & 3;                 // float4 within BK
            int arow = row0 + r;
            if (arow >= NN) arow = NN - 1;
            float4 av = *(const float4*)&X[arow * K + k0 + kv * 4];
            As[kv * 4 + 0][r] = av.x;
            As[kv * 4 + 1][r] = av.y;
            As[kv * 4 + 2][r] = av.z;
            As[kv * 4 + 3][r] = av.w;
        }
        // load B tile: BK x BN floats
        if (BN == 128) {
            #pragma unroll
            for (int l = 0; l < 2; l++) {
                int f = tid + l * 256;      // 0..511
                int rk = f >> 5;            // 0..15
                int c4 = f & 31;            // 0..31
                *(float4*)&Bs[rk][c4 * 4] = *(const float4*)&W[(k0 + rk) * HOUT + c4 * 4];
            }
        } else {                             // BN == 64: 256 float4
            int rk = tid >> 4;              // 0..15
            int c4 = tid & 15;              // 0..15
            *(float4*)&Bs[rk][c4 * 4] = *(const float4*)&W[(k0 + rk) * HOUT + c4 * 4];
        }
        __syncthreads();

        #pragma unroll
        for (int kk = 0; kk < BK; kk++) {
            // a scalars -> broadcast-packed {a,a}
            float a[TM];
            #pragma unroll
            for (int i = 0; i < TM; i += 4) {
                float4 a4 = *(float4*)&As[kk][ty * TM + i];
                a[i] = a4.x; a[i+1] = a4.y; a[i+2] = a4.z; a[i+3] = a4.w;
            }
            unsigned long long a2[TM];
            #pragma unroll
            for (int i = 0; i < TM; i++)
                asm("mov.b64 %0, {%1, %1};" : "=l"(a2[i]) : "f"(a[i]));
            // b pairs straight from shared as 64-bit values
            unsigned long long b2[TN2];
            const unsigned long long* bp =
                (const unsigned long long*)&Bs[kk][tx * TN];
            #pragma unroll
            for (int j = 0; j < TN2; j++) b2[j] = bp[j];
            // packed FMA: 2 fp32 FMAs per instruction
            #pragma unroll
            for (int i = 0; i < TM; i++)
                #pragma unroll
                for (int j = 0; j < TN2; j++)
                    asm("fma.rn.f32x2 %0, %1, %2, %0;"
                        : "+l"(acc2[i][j]) : "l"(a2[i]), "l"(b2[j]));
        }
        __syncthreads();
    }

    // unpack, bias, relu, store (float or half)
    float bs[TN];
    #pragma unroll
    for (int j = 0; j < TN; j++) bs[j] = B[tx * TN + j];

    #pragma unroll
    for (int i = 0; i < TM; i++) {
        int r = row0 + ty * TM + i;
        if (r < NN) {
            float v[TN];
            #pragma unroll
            for (int j = 0; j < TN2; j++)
                asm("mov.b64 {%0, %1}, %2;"
                    : "=f"(v[2*j]), "=f"(v[2*j+1]) : "l"(acc2[i][j]));
            #pragma unroll
            for (int j = 0; j < TN; j++) v[j] = fmaxf(v[j] + bs[j], 0.0f);
            if (HALF_OUT) {
                #pragma unroll
                for (int j = 0; j < TN; j += 2)
                    *(__half2*)&g_xh[r * HOUT + tx * TN + j] =
                        __floats2half2_rn(v[j], v[j + 1]);
            } else {
                float* Y = gbuf(DST);
                #pragma unroll
                for (int j = 0; j < TN; j += 4) {
                    float4 o = make_float4(v[j], v[j+1], v[j+2], v[j+3]);
                    *(float4*)&Y[r * HOUT + tx * TN + j] = o;
                }
            }
        }
    }
}

// ---------------- final FC (N,64)@(64,8)+b and emb copy ----------------
template <int SRC>
__global__ void k_fc(const float* __restrict__ W,
                     const float* __restrict__ B,
                     float* __restrict__ out,
                     float* __restrict__ emb) {
    int gw = (blockIdx.x * blockDim.x + threadIdx.x) >> 5;
    if (gw >= NN) return;
    int lane = threadIdx.x & 31;
    const float* X = gbuf(SRC);
    float v0 = X[gw * 64 + lane];
    float v1 = X[gw * 64 + 32 + lane];
    emb[gw * 64 + lane] = v0;
    emb[gw * 64 + 32 + lane] = v1;
    #pragma unroll
    for (int j = 0; j < 8; j++) {
        float p = v0 * W[lane * 8 + j] + v1 * W[(lane + 32) * 8 + j];
        #pragma unroll
        for (int o = 16; o > 0; o >>= 1)
            p += __shfl_down_sync(0xffffffffu, p, o);
        if (lane == 0) out[gw * 8 + j] = p + B[j];
    }
}

// ---------------- launch ----------------
extern "C" void kernel_launch(void* const* d_in, const int* in_sizes, int n_in,
                              void* d_out, int out_size) {
    const float* x    = (const float*)d_in[0];
    const void*  ei   = d_in[1];
    const float* eps1 = (const float*)d_in[2];
    const float* eps2 = (const float*)d_in[3];
    const float* eps3 = (const float*)d_in[4];
    const float* W1a  = (const float*)d_in[5];
    const float* b1a  = (const float*)d_in[6];
    const float* W1b  = (const float*)d_in[7];
    const float* b1b  = (const float*)d_in[8];
    const float* W2a  = (const float*)d_in[9];
    const float* b2a  = (const float*)d_in[10];
    const float* W2b  = (const float*)d_in[11];
    const float* b2b  = (const float*)d_in[12];
    const float* W3a  = (const float*)d_in[13];
    const float* b3a  = (const float*)d_in[14];
    const float* W3b  = (const float*)d_in[15];
    const float* b3b  = (const float*)d_in[16];
    const float* Wfc  = (const float*)d_in[17];
    const float* bfc  = (const float*)d_in[18];

    float* out = (float*)d_out;             // (N, 8)
    float* emb = out + NN * 8;              // (N, 64)

    // CSR build
    k_detect<<<1, 1024>>>((const long long*)ei);
    k_zero_deg<<<(NN + 255) / 256, 256>>>();
    k_hist<<<(EE + 255) / 256, 256>>>(ei);
    k_block_sums<<<SCAN_NB, SCAN_BLK>>>();
    k_scan_parts<<<1, 128>>>();
    k_scan_final<<<SCAN_NB, SCAN_BLK>>>();
    k_fill<<<(EE + 255) / 256, 256>>>(ei);

    // input to fp16 (gather source for layer 1)
    k_x2h<<<(NN * 32 + 255) / 256, 256>>>(x);

    const int aggBlocks = (NN * 32 + 255) / 256;
    const int gemmBlocks = (NN + 127) / 128;

    // Layer 1: 64 -> 128 -> 128 (half out for next gather)
    k_aggh<64><<<aggBlocks, 256>>>(eps1);
    k_gemm<64, 128, 0, 1, false><<<gemmBlocks, 256>>>(W1a, b1a);
    k_gemm<128, 128, 1, 2, true><<<gemmBlocks, 256>>>(W1b, b1b);

    // Layer 2: 128 -> 128 -> 128 (half out for next gather)
    k_aggh<128><<<aggBlocks, 256>>>(eps2);
    k_gemm<128, 128, 0, 1, false><<<gemmBlocks, 256>>>(W2a, b2a);
    k_gemm<128, 128, 1, 2, true><<<gemmBlocks, 256>>>(W2b, b2b);

    // Layer 3: 128 -> 64 -> 64 (float out to g_x for fc/emb)
    k_aggh<128><<<aggBlocks, 256>>>(eps3);
    k_gemm<128, 64, 0, 1, false><<<gemmBlocks, 256>>>(W3a, b3a);
    k_gemm<64, 64, 1, 2, false><<<gemmBlocks, 256>>>(W3b, b3b);

    // FC + emb
    k_fc<2><<<aggBlocks, 256>>>(Wfc, bfc, out, emb);
}

// round 14
// speedup vs baseline: 2.3828x; 1.8023x over previous
#include <cuda_runtime.h>
#include <cuda_fp16.h>
#include <cstdint>

#define NN 100000
#define EE 1600000
#define SCAN_BLK 1024
#define SCAN_NB ((NN + SCAN_BLK - 1) / SCAN_BLK)   // 98

#define SCL 256.0f      // fp16 storage scale for agg/mid tensors (power of two: exact)
#define SCLI (1.0f / 256.0f)

// ---------------- scratch (no allocations allowed) ----------------
__device__ int    g_is64;
__device__ int    g_deg[NN];
__device__ int    g_off[NN];
__device__ int    g_cur[NN];
__device__ int    g_csr[EE];
__device__ int    g_part[128];
__device__ int    g_partoff[128];
__device__ float  g_x[NN * 128];     // final layer fp32 out (fc/emb source)
__device__ __half g_ha[NN * 128];    // agg out (GEMM-A input), fp16, scaled by 1/SCL
__device__ __half g_th[NN * 128];    // MLP mid, fp16, scaled by 1/SCL
__device__ __half g_xh[NN * 128];    // layer activations (gather source), fp16, unscaled
__device__ __half g_wh[69632];       // fp16 weights: W1a|W1b|W2a|W2b|W3a|W3b

__device__ __forceinline__ __half* hbuf(int i) {
    return (i == 0) ? g_ha : (i == 1) ? g_th : g_xh;
}

// ---------------- dtype detection (int64 vs silently-downcast int32) ----------------
__global__ void k_detect(const long long* __restrict__ e64) {
    __shared__ int bad;
    if (threadIdx.x == 0) bad = 0;
    __syncthreads();
    for (int i = threadIdx.x; i < 4096; i += blockDim.x) {
        long long v = e64[i];
        if (v < 0 || v >= NN) bad = 1;
    }
    __syncthreads();
    if (threadIdx.x == 0) g_is64 = bad ? 0 : 1;
}

// ---------------- CSR build ----------------
__global__ void k_zero_deg() {
    int i = blockIdx.x * blockDim.x + threadIdx.x;
    if (i < NN) g_deg[i] = 0;
}

__device__ __forceinline__ int edge_at(const void* ei, int idx) {
    if (g_is64) return (int)((const long long*)ei)[idx];
    return ((const int*)ei)[idx];
}

__global__ void k_hist(const void* __restrict__ ei) {
    int e = blockIdx.x * blockDim.x + threadIdx.x;
    if (e < EE) {
        int d = edge_at(ei, EE + e);
        if ((unsigned)d < (unsigned)NN) atomicAdd(&g_deg[d], 1);
    }
}

__global__ void k_block_sums() {
    int i = blockIdx.x * SCAN_BLK + threadIdx.x;
    int v = (i < NN) ? g_deg[i] : 0;
    #pragma unroll
    for (int o = 16; o > 0; o >>= 1) v += __shfl_down_sync(0xffffffffu, v, o);
    __shared__ int ws[32];
    int wid = threadIdx.x >> 5, lane = threadIdx.x & 31;
    if (lane == 0) ws[wid] = v;
    __syncthreads();
    if (wid == 0) {
        int s = ws[lane];
        #pragma unroll
        for (int o = 16; o > 0; o >>= 1) s += __shfl_down_sync(0xffffffffu, s, o);
        if (lane == 0) g_part[blockIdx.x] = s;
    }
}

__global__ void k_scan_parts() {
    __shared__ int sm[128];
    int t = threadIdx.x;
    int v = (t < SCAN_NB) ? g_part[t] : 0;
    sm[t] = v;
    __syncthreads();
    #pragma unroll
    for (int o = 1; o < 128; o <<= 1) {
        int u = (t >= o) ? sm[t - o] : 0;
        __syncthreads();
        sm[t] += u;
        __syncthreads();
    }
    g_partoff[t] = sm[t] - v;   // exclusive
}

__global__ void k_scan_final() {
    int i = blockIdx.x * SCAN_BLK + threadIdx.x;
    int v = (i < NN) ? g_deg[i] : 0;
    int wid = threadIdx.x >> 5, lane = threadIdx.x & 31;
    int incl = v;
    #pragma unroll
    for (int o = 1; o < 32; o <<= 1) {
        int u = __shfl_up_sync(0xffffffffu, incl, o);
        if (lane >= o) incl += u;
    }
    __shared__ int ws[32];
    if (lane == 31) ws[wid] = incl;
    __syncthreads();
    if (wid == 0) {
        int s = ws[lane];
        #pragma unroll
        for (int o = 1; o < 32; o <<= 1) {
            int u = __shfl_up_sync(0xffffffffu, s, o);
            if (lane >= o) s += u;
        }
        ws[lane] = s - ws[lane];
    }
    __syncthreads();
    if (i < NN) {
        int e = incl - v + ws[wid] + g_partoff[blockIdx.x];
        g_off[i] = e;
        g_cur[i] = e;
    }
}

__global__ void k_fill(const void* __restrict__ ei) {
    int e = blockIdx.x * blockDim.x + threadIdx.x;
    if (e < EE) {
        int d = edge_at(ei, EE + e);
        int s = edge_at(ei, e);
        if ((unsigned)d < (unsigned)NN && (unsigned)s < (unsigned)NN) {
            int p = atomicAdd(&g_cur[d], 1);
            if ((unsigned)p < (unsigned)EE) g_csr[p] = s;
        }
    }
}

// ---------------- x (fp32) -> g_xh (fp16) for layer-1 gather ----------------
__global__ void k_x2h(const float* __restrict__ x) {
    int i = blockIdx.x * blockDim.x + threadIdx.x;
    if (i < NN * 32) {
        float2 f = ((const float2*)x)[i];
        ((__half2*)g_xh)[i] = __floats2half2_rn(f.x, f.y);
    }
}

// ---------------- weights fp32 -> fp16 (once per launch) ----------------
__global__ void k_w2h(const float* __restrict__ W1a, const float* __restrict__ W1b,
                      const float* __restrict__ W2a, const float* __restrict__ W2b,
                      const float* __restrict__ W3a, const float* __restrict__ W3b) {
    int i = blockIdx.x * blockDim.x + threadIdx.x;
    if (i >= 69632) return;
    float v;
    if      (i < 8192)  v = W1a[i];
    else if (i < 24576) v = W1b[i - 8192];
    else if (i < 40960) v = W2a[i - 24576];
    else if (i < 57344) v = W2b[i - 40960];
    else if (i < 65536) v = W3a[i - 57344];
    else                v = W3b[i - 65536];
    g_wh[i] = __float2half(v);
}

// -------- aggregation (fp16 gather, fp32 accum, scaled fp16 store to g_ha) --------
template <int F>
__global__ void k_aggh(const float* __restrict__ epsp) {
    int gw = (blockIdx.x * blockDim.x + threadIdx.x) >> 5;
    if (gw >= NN) return;
    int lane = threadIdx.x & 31;
    float scale = 1.0f + __ldg(epsp);
    int start = g_off[gw];
    int end = g_cur[gw];
    if (start < 0) start = 0;
    if (end > EE) end = EE;
    if (end < start) end = start;

    if (F == 128) {
        const uint2* xh = (const uint2*)g_xh;   // 4 halfs / uint2; row = 32 uint2
        uint2 sv = xh[gw * 32 + lane];
        float2 s0 = __half22float2(*reinterpret_cast<__half2*>(&sv.x));
        float2 s1 = __half22float2(*reinterpret_cast<__half2*>(&sv.y));
        float4 acc = make_float4(s0.x * scale, s0.y * scale, s1.x * scale, s1.y * scale);
        for (int j = start; j < end; j++) {
            uint2 v = xh[g_csr[j] * 32 + lane];
            float2 f0 = __half22float2(*reinterpret_cast<__half2*>(&v.x));
            float2 f1 = __half22float2(*reinterpret_cast<__half2*>(&v.y));
            acc.x += f0.x; acc.y += f0.y; acc.z += f1.x; acc.w += f1.y;
        }
        uint2 o;
        *reinterpret_cast<__half2*>(&o.x) = __floats2half2_rn(acc.x * SCLI, acc.y * SCLI);
        *reinterpret_cast<__half2*>(&o.y) = __floats2half2_rn(acc.z * SCLI, acc.w * SCLI);
        ((uint2*)g_ha)[gw * 32 + lane] = o;
    } else {                                    // F == 64: row = 32 half2
        const __half2* xh = (const __half2*)g_xh;
        float2 s = __half22float2(xh[gw * 32 + lane]);
        float2 acc = make_float2(s.x * scale, s.y * scale);
        for (int j = start; j < end; j++) {
            float2 f = __half22float2(xh[g_csr[j] * 32 + lane]);
            acc.x += f.x; acc.y += f.y;
        }
        ((__half2*)g_ha)[gw * 32 + lane] = __floats2half2_rn(acc.x * SCLI, acc.y * SCLI);
    }
}

// ---------------- tensor-core GEMM: Y = relu(A*ASC @ W + bias) ----------------
// A = hbuf(SRC) fp16 [NN x K] (scaled by 1/SCL when ASCALED); W = g_wh+WOFF fp16.
// mma.sync.m16n8k16 f16*f16+f32. BM=128, BN=HOUT, BK=32, 256 threads (8 warps).
// OSCALE: store v/SCL (half); HALF_OUT -> hbuf(HDST), else g_x (fp32, unscaled).
template <int K, int HOUT, int SRC, int WOFF, bool HALF_OUT, int HDST,
          bool ASCALED, bool OSCALE>
__global__ __launch_bounds__(256) void k_gmma(const float* __restrict__ Bias) {
    const int BM = 128, BN = HOUT, BK = 32;
    const int APAD = BK + 8;                 // 40 halfs
    const int BPAD = BN + 8;                 // 136 or 72 halfs
    const int WN = (BN == 128) ? 64 : 32;    // warp n width
    const int NT = WN / 8;                   // n tiles per warp: 8 or 4
    const int NP = NT / 2;                   // x4.trans loads per k-step: 4 or 2
    __shared__ __align__(16) __half As[BM][APAD];
    __shared__ __align__(16) __half Bs[BK][BPAD];

    const __half* A = hbuf(SRC);
    const __half* W = g_wh + WOFF;

    int tid = threadIdx.x;
    int wid = tid >> 5, lane = tid & 31;
    int warp_m = wid & 3;
    int warp_n = wid >> 2;
    int row0 = blockIdx.x * BM;

    float acc[2][NT][4];
    #pragma unroll
    for (int tm = 0; tm < 2; tm++)
        #pragma unroll
        for (int tn = 0; tn < NT; tn++)
            #pragma unroll
            for (int q = 0; q < 4; q++) acc[tm][tn][q] = 0.0f;

    for (int k0 = 0; k0 < K; k0 += BK) {
        // A tile: 128 rows x 32 halfs = 512 uint4 (8 halfs each), 2 per thread
        #pragma unroll
        for (int l = 0; l < 2; l++) {
            int f = tid + l * 256;           // 0..511
            int r = f >> 2;                  // 0..127
            int seg = f & 3;                 // uint4 segment within the 32-half row
            int arow = row0 + r; if (arow >= NN) arow = NN - 1;
            *(uint4*)&As[r][seg * 8] = *(const uint4*)&A[arow * K + k0 + seg * 8];
        }
        if (BN == 128) {                     // 32 x 128 halfs = 512 uint4, 2/thread
            #pragma unroll
            for (int l = 0; l < 2; l++) {
                int f = tid + l * 256;
                int rk = f >> 4, c8 = f & 15;
                *(uint4*)&Bs[rk][c8 * 8] = *(const uint4*)&W[(k0 + rk) * HOUT + c8 * 8];
            }
        } else {                             // 32 x 64 halfs = 256 uint4, 1/thread
            int rk = tid >> 3, c8 = tid & 7;
            *(uint4*)&Bs[rk][c8 * 8] = *(const uint4*)&W[(k0 + rk) * HOUT + c8 * 8];
        }
        __syncthreads();

        #pragma unroll
        for (int ks = 0; ks < 2; ks++) {     // two k16 steps per BK=32
            uint32_t a[2][4];
            #pragma unroll
            for (int tm = 0; tm < 2; tm++) {
                const __half* p = &As[warp_m * 32 + tm * 16 + (lane & 15)]
                                     [ks * 16 + (lane >> 4) * 8];
                uint32_t ad = (uint32_t)__cvta_generic_to_shared(p);
                asm volatile("ldmatrix.sync.aligned.m8n8.x4.shared.b16 {%0,%1,%2,%3}, [%4];"
                             : "=r"(a[tm][0]), "=r"(a[tm][1]), "=r"(a[tm][2]), "=r"(a[tm][3])
                             : "r"(ad));
            }
            #pragma unroll
            for (int np = 0; np < NP; np++) {
                uint32_t b[4];
                const __half* p = &Bs[ks * 16 + (lane & 15)]
                                     [warp_n * WN + np * 16 + (lane >> 4) * 8];
                uint32_t ad = (uint32_t)__cvta_generic_to_shared(p);
                asm volatile("ldmatrix.sync.aligned.m8n8.x4.trans.shared.b16 {%0,%1,%2,%3}, [%4];"
                             : "=r"(b[0]), "=r"(b[1]), "=r"(b[2]), "=r"(b[3])
                             : "r"(ad));
                #pragma unroll
                for (int tm = 0; tm < 2; tm++) {
                    asm volatile(
                        "mma.sync.aligned.m16n8k16.row.col.f32.f16.f16.f32 "
                        "{%0,%1,%2,%3}, {%4,%5,%6,%7}, {%8,%9}, {%0,%1,%2,%3};"
                        : "+f"(acc[tm][np * 2][0]), "+f"(acc[tm][np * 2][1]),
                          "+f"(acc[tm][np * 2][2]), "+f"(acc[tm][np * 2][3])
                        : "r"(a[tm][0]), "r"(a[tm][1]), "r"(a[tm][2]), "r"(a[tm][3]),
                          "r"(b[0]), "r"(b[1]));
                    asm volatile(
                        "mma.sync.aligned.m16n8k16.row.col.f32.f16.f16.f32 "
                        "{%0,%1,%2,%3}, {%4,%5,%6,%7}, {%8,%9}, {%0,%1,%2,%3};"
                        : "+f"(acc[tm][np * 2 + 1][0]), "+f"(acc[tm][np * 2 + 1][1]),
                          "+f"(acc[tm][np * 2 + 1][2]), "+f"(acc[tm][np * 2 + 1][3])
                        : "r"(a[tm][0]), "r"(a[tm][1]), "r"(a[tm][2]), "r"(a[tm][3]),
                          "r"(b[2]), "r"(b[3]));
                }
            }
        }
        __syncthreads();
    }

    // epilogue: unscale, bias + relu; half (maybe rescaled) or float store
    const float ASC = ASCALED ? SCL : 1.0f;
    const float OSC = OSCALE ? SCLI : 1.0f;
    int qid = lane >> 2;     // row within 8
    int tq = lane & 3;       // col pair index
    #pragma unroll
    for (int tm = 0; tm < 2; tm++) {
        #pragma unroll
        for (int tn = 0; tn < NT; tn++) {
            int c = warp_n * WN + tn * 8 + tq * 2;
            float2 bb = *(const float2*)&Bias[c];
            #pragma unroll
            for (int h = 0; h < 2; h++) {
                int r = row0 + warp_m * 32 + tm * 16 + qid + h * 8;
                if (r < NN) {
                    float v0 = fmaxf(acc[tm][tn][h * 2 + 0] * ASC + bb.x, 0.0f);
                    float v1 = fmaxf(acc[tm][tn][h * 2 + 1] * ASC + bb.y, 0.0f);
                    if (HALF_OUT) {
                        *(__half2*)&hbuf(HDST)[r * HOUT + c] =
                            __floats2half2_rn(v0 * OSC, v1 * OSC);
                    } else {
                        *(float2*)&g_x[r * HOUT + c] = make_float2(v0, v1);
                    }
                }
            }
        }
    }
}

// ---------------- final FC (N,64)@(64,8)+b and emb copy ----------------
__global__ void k_fc(const float* __restrict__ W,
                     const float* __restrict__ B,
                     float* __restrict__ out,
                     float* __restrict__ emb) {
    int gw = (blockIdx.x * blockDim.x + threadIdx.x) >> 5;
    if (gw >= NN) return;
    int lane = threadIdx.x & 31;
    float v0 = g_x[gw * 64 + lane];
    float v1 = g_x[gw * 64 + 32 + lane];
    emb[gw * 64 + lane] = v0;
    emb[gw * 64 + 32 + lane] = v1;
    #pragma unroll
    for (int j = 0; j < 8; j++) {
        float p = v0 * W[lane * 8 + j] + v1 * W[(lane + 32) * 8 + j];
        #pragma unroll
        for (int o = 16; o > 0; o >>= 1)
            p += __shfl_down_sync(0xffffffffu, p, o);
        if (lane == 0) out[gw * 8 + j] = p + B[j];
    }
}

// ---------------- launch ----------------
extern "C" void kernel_launch(void* const* d_in, const int* in_sizes, int n_in,
                              void* d_out, int out_size) {
    const float* x    = (const float*)d_in[0];
    const void*  ei   = d_in[1];
    const float* eps1 = (const float*)d_in[2];
    const float* eps2 = (const float*)d_in[3];
    const float* eps3 = (const float*)d_in[4];
    const float* W1a  = (const float*)d_in[5];
    const float* b1a  = (const float*)d_in[6];
    const float* W1b  = (const float*)d_in[7];
    const float* b1b  = (const float*)d_in[8];
    const float* W2a  = (const float*)d_in[9];
    const float* b2a  = (const float*)d_in[10];
    const float* W2b  = (const float*)d_in[11];
    const float* b2b  = (const float*)d_in[12];
    const float* W3a  = (const float*)d_in[13];
    const float* b3a  = (const float*)d_in[14];
    const float* W3b  = (const float*)d_in[15];
    const float* b3b  = (const float*)d_in[16];
    const float* Wfc  = (const float*)d_in[17];
    const float* bfc  = (const float*)d_in[18];

    float* out = (float*)d_out;             // (N, 8)
    float* emb = out + NN * 8;              // (N, 64)

    // CSR build
    k_detect<<<1, 1024>>>((const long long*)ei);
    k_zero_deg<<<(NN + 255) / 256, 256>>>();
    k_hist<<<(EE + 255) / 256, 256>>>(ei);
    k_block_sums<<<SCAN_NB, SCAN_BLK>>>();
    k_scan_parts<<<1, 128>>>();
    k_scan_final<<<SCAN_NB, SCAN_BLK>>>();
    k_fill<<<(EE + 255) / 256, 256>>>(ei);

    // fp16 conversions
    k_x2h<<<(NN * 32 + 255) / 256, 256>>>(x);
    k_w2h<<<(69632 + 255) / 256, 256>>>(W1a, W1b, W2a, W2b, W3a, W3b);

    const int aggBlocks = (NN * 32 + 255) / 256;
    const int gemmBlocks = (NN + 127) / 128;

    // Weight offsets in g_wh: W1a=0 W1b=8192 W2a=24576 W2b=40960 W3a=57344 W3b=65536
    // Scaling: g_ha, g_th hold value/SCL; g_xh, g_x hold true values.

    // Layer 1: 64 -> 128 -> 128
    k_aggh<64><<<aggBlocks, 256>>>(eps1);
    k_gmma<64, 128, 0, 0, true, 1, true, true><<<gemmBlocks, 256>>>(b1a);
    k_gmma<128, 128, 1, 8192, true, 2, true, false><<<gemmBlocks, 256>>>(b1b);

    // Layer 2: 128 -> 128 -> 128
    k_aggh<128><<<aggBlocks, 256>>>(eps2);
    k_gmma<128, 128, 0, 24576, true, 1, true, true><<<gemmBlocks, 256>>>(b2a);
    k_gmma<128, 128, 1, 40960, true, 2, true, false><<<gemmBlocks, 256>>>(b2b);

    // Layer 3: 128 -> 64 -> 64 (final GEMM fp32 out to g_x)
    k_aggh<128><<<aggBlocks, 256>>>(eps3);
    k_gmma<128, 64, 0, 57344, true, 1, true, true><<<gemmBlocks, 256>>>(b3a);
    k_gmma<64, 64, 1, 65536, false, 0, true, false><<<gemmBlocks, 256>>>(b3b);

    // FC + emb
    k_fc<<<aggBlocks, 256>>>(Wfc, bfc, out, emb);
}

// round 15
// speedup vs baseline: 2.5348x; 1.0638x over previous
#include <cuda_runtime.h>
#include <cuda_fp16.h>
#include <cstdint>

#define NN 100000
#define EE 1600000
#define SCAN_BLK 1024
#define SCAN_NB ((NN + SCAN_BLK - 1) / SCAN_BLK)   // 98

#define SCL 256.0f      // fp16 storage scale for agg/mid tensors (power of two: exact)
#define SCLI (1.0f / 256.0f)

// ---------------- scratch (no allocations allowed) ----------------
__device__ int    g_is64;
__device__ int    g_deg[NN];
__device__ int    g_off[NN];
__device__ int    g_cur[NN];
__device__ int    g_csr[EE];
__device__ int    g_part[128];
__device__ int    g_partoff[128];
__device__ float  g_x[NN * 128];     // final layer fp32 out (fc/emb source)
__device__ __half g_ha[NN * 128];    // agg out (MLP input), fp16, scaled by 1/SCL
__device__ __half g_xh[NN * 128];    // layer activations (gather source), fp16, unscaled
__device__ __half g_wh[69632];       // fp16 weights: W1a|W1b|W2a|W2b|W3a|W3b

// ---------------- dtype detection (int64 vs silently-downcast int32) ----------------
__global__ void k_detect(const long long* __restrict__ e64) {
    __shared__ int bad;
    if (threadIdx.x == 0) bad = 0;
    __syncthreads();
    for (int i = threadIdx.x; i < 4096; i += blockDim.x) {
        long long v = e64[i];
        if (v < 0 || v >= NN) bad = 1;
    }
    __syncthreads();
    if (threadIdx.x == 0) g_is64 = bad ? 0 : 1;
}

// ---------------- CSR build ----------------
__global__ void k_zero_deg() {
    int i = blockIdx.x * blockDim.x + threadIdx.x;
    if (i < NN) g_deg[i] = 0;
}

__device__ __forceinline__ int edge_at(const void* ei, int idx) {
    if (g_is64) return (int)((const long long*)ei)[idx];
    return ((const int*)ei)[idx];
}

__global__ void k_hist(const void* __restrict__ ei) {
    int e = blockIdx.x * blockDim.x + threadIdx.x;
    if (e < EE) {
        int d = edge_at(ei, EE + e);
        if ((unsigned)d < (unsigned)NN) atomicAdd(&g_deg[d], 1);
    }
}

__global__ void k_block_sums() {
    int i = blockIdx.x * SCAN_BLK + threadIdx.x;
    int v = (i < NN) ? g_deg[i] : 0;
    #pragma unroll
    for (int o = 16; o > 0; o >>= 1) v += __shfl_down_sync(0xffffffffu, v, o);
    __shared__ int ws[32];
    int wid = threadIdx.x >> 5, lane = threadIdx.x & 31;
    if (lane == 0) ws[wid] = v;
    __syncthreads();
    if (wid == 0) {
        int s = ws[lane];
        #pragma unroll
        for (int o = 16; o > 0; o >>= 1) s += __shfl_down_sync(0xffffffffu, s, o);
        if (lane == 0) g_part[blockIdx.x] = s;
    }
}

__global__ void k_scan_parts() {
    __shared__ int sm[128];
    int t = threadIdx.x;
    int v = (t < SCAN_NB) ? g_part[t] : 0;
    sm[t] = v;
    __syncthreads();
    #pragma unroll
    for (int o = 1; o < 128; o <<= 1) {
        int u = (t >= o) ? sm[t - o] : 0;
        __syncthreads();
        sm[t] += u;
        __syncthreads();
    }
    g_partoff[t] = sm[t] - v;   // exclusive
}

__global__ void k_scan_final() {
    int i = blockIdx.x * SCAN_BLK + threadIdx.x;
    int v = (i < NN) ? g_deg[i] : 0;
    int wid = threadIdx.x >> 5, lane = threadIdx.x & 31;
    int incl = v;
    #pragma unroll
    for (int o = 1; o < 32; o <<= 1) {
        int u = __shfl_up_sync(0xffffffffu, incl, o);
        if (lane >= o) incl += u;
    }
    __shared__ int ws[32];
    if (lane == 31) ws[wid] = incl;
    __syncthreads();
    if (wid == 0) {
        int s = ws[lane];
        #pragma unroll
        for (int o = 1; o < 32; o <<= 1) {
            int u = __shfl_up_sync(0xffffffffu, s, o);
            if (lane >= o) s += u;
        }
        ws[lane] = s - ws[lane];
    }
    __syncthreads();
    if (i < NN) {
        int e = incl - v + ws[wid] + g_partoff[blockIdx.x];
        g_off[i] = e;
        g_cur[i] = e;
    }
}

__global__ void k_fill(const void* __restrict__ ei) {
    int e = blockIdx.x * blockDim.x + threadIdx.x;
    if (e < EE) {
        int d = edge_at(ei, EE + e);
        int s = edge_at(ei, e);
        if ((unsigned)d < (unsigned)NN && (unsigned)s < (unsigned)NN) {
            int p = atomicAdd(&g_cur[d], 1);
            if ((unsigned)p < (unsigned)EE) g_csr[p] = s;
        }
    }
}

// ---------------- x (fp32) -> g_xh (fp16) for layer-1 gather ----------------
__global__ void k_x2h(const float* __restrict__ x) {
    int i = blockIdx.x * blockDim.x + threadIdx.x;
    if (i < NN * 32) {
        float2 f = ((const float2*)x)[i];
        ((__half2*)g_xh)[i] = __floats2half2_rn(f.x, f.y);
    }
}

// ---------------- weights fp32 -> fp16 (once per launch) ----------------
__global__ void k_w2h(const float* __restrict__ W1a, const float* __restrict__ W1b,
                      const float* __restrict__ W2a, const float* __restrict__ W2b,
                      const float* __restrict__ W3a, const float* __restrict__ W3b) {
    int i = blockIdx.x * blockDim.x + threadIdx.x;
    if (i >= 69632) return;
    float v;
    if      (i < 8192)  v = W1a[i];
    else if (i < 24576) v = W1b[i - 8192];
    else if (i < 40960) v = W2a[i - 24576];
    else if (i < 57344) v = W2b[i - 40960];
    else if (i < 65536) v = W3a[i - 57344];
    else                v = W3b[i - 65536];
    g_wh[i] = __float2half(v);
}

// -------- aggregation (fp16 gather, fp32 accum, scaled fp16 store to g_ha) --------
template <int F>
__global__ void k_aggh(const float* __restrict__ epsp) {
    int gw = (blockIdx.x * blockDim.x + threadIdx.x) >> 5;
    if (gw >= NN) return;
    int lane = threadIdx.x & 31;
    float scale = 1.0f + __ldg(epsp);
    int start = g_off[gw];
    int end = g_cur[gw];
    if (start < 0) start = 0;
    if (end > EE) end = EE;
    if (end < start) end = start;

    if (F == 128) {
        const uint2* xh = (const uint2*)g_xh;   // 4 halfs / uint2; row = 32 uint2
        uint2 sv = xh[gw * 32 + lane];
        float2 s0 = __half22float2(*reinterpret_cast<__half2*>(&sv.x));
        float2 s1 = __half22float2(*reinterpret_cast<__half2*>(&sv.y));
        float4 acc = make_float4(s0.x * scale, s0.y * scale, s1.x * scale, s1.y * scale);
        for (int j = start; j < end; j++) {
            uint2 v = xh[g_csr[j] * 32 + lane];
            float2 f0 = __half22float2(*reinterpret_cast<__half2*>(&v.x));
            float2 f1 = __half22float2(*reinterpret_cast<__half2*>(&v.y));
            acc.x += f0.x; acc.y += f0.y; acc.z += f1.x; acc.w += f1.y;
        }
        uint2 o;
        *reinterpret_cast<__half2*>(&o.x) = __floats2half2_rn(acc.x * SCLI, acc.y * SCLI);
        *reinterpret_cast<__half2*>(&o.y) = __floats2half2_rn(acc.z * SCLI, acc.w * SCLI);
        ((uint2*)g_ha)[gw * 32 + lane] = o;
    } else {                                    // F == 64: row = 32 half2
        const __half2* xh = (const __half2*)g_xh;
        float2 s = __half22float2(xh[gw * 32 + lane]);
        float2 acc = make_float2(s.x * scale, s.y * scale);
        for (int j = start; j < end; j++) {
            float2 f = __half22float2(xh[g_csr[j] * 32 + lane]);
            acc.x += f.x; acc.y += f.y;
        }
        ((__half2*)g_ha)[gw * 32 + lane] = __floats2half2_rn(acc.x * SCLI, acc.y * SCLI);
    }
}

// ---------------- fused MLP: out = relu(relu(A*SCL @ Wa + ba) @ Wb + bb) ----------------
// A = g_ha fp16 [NN x K1], scaled 1/SCL. Wa = g_wh+WOFFA [K1 x H], Wb = g_wh+WOFFB [H x HOUT].
// Mid never leaves shared memory (stored fp16, scaled 1/SCL — same numerics as before).
// HALF_OUT: write g_xh (fp16, unscaled); else g_x (fp32).
// 256 threads, BM=128, warp grid 4(m) x 2(n). H, HOUT in {128, 64}, H == HOUT.
template <int K1, int H, int HOUT, int WOFFA, int WOFFB, bool HALF_OUT>
__global__ __launch_bounds__(256) void k_mlp(const float* __restrict__ Ba,
                                             const float* __restrict__ Bb) {
    const int BM = 128;
    const int APAD = 24;                     // 16 + 8 halfs (48 B rows)
    const int BPAD = H + 8;                  // W tile / Mid padded stride (16B-aligned)
    const int WN = (H == 128) ? 64 : 32;     // warp n width
    const int NT = WN / 8;                   // 8 or 4
    const int NP = NT / 2;                   // 4 or 2
    __shared__ __align__(16) __half As[BM][APAD];    // 6 KB
    __shared__ __align__(16) __half Bs[16][BPAD];    // 4.25 KB (H=128)
    __shared__ __align__(16) __half Mid[BM][BPAD];   // 34 KB (H=128)

    const __half* A  = g_ha;
    const __half* Wa = g_wh + WOFFA;
    const __half* Wb = g_wh + WOFFB;

    int tid = threadIdx.x;
    int wid = tid >> 5, lane = tid & 31;
    int warp_m = wid & 3;
    int warp_n = wid >> 2;
    int row0 = blockIdx.x * BM;
    int qid = lane >> 2;     // epilogue row within 8
    int tq = lane & 3;       // epilogue col pair

    // ---------------- stage 1: mid = relu(A*SCL @ Wa + ba), kept in smem ----------------
    {
        float acc[2][NT][4];
        #pragma unroll
        for (int tm = 0; tm < 2; tm++)
            #pragma unroll
            for (int tn = 0; tn < NT; tn++)
                #pragma unroll
                for (int q = 0; q < 4; q++) acc[tm][tn][q] = 0.0f;

        for (int k0 = 0; k0 < K1; k0 += 16) {
            // A tile: 128 x 16 halfs = 256 uint4, 1/thread
            {
                int r = tid >> 1, seg = tid & 1;
                int arow = row0 + r; if (arow >= NN) arow = NN - 1;
                *(uint4*)&As[r][seg * 8] = *(const uint4*)&A[arow * K1 + k0 + seg * 8];
            }
            // Wa tile: 16 x H halfs
            if (H == 128) {
                int rk = tid >> 4, c8 = tid & 15;
                *(uint4*)&Bs[rk][c8 * 8] = *(const uint4*)&Wa[(k0 + rk) * H + c8 * 8];
            } else if (tid < 128) {
                int rk = tid >> 3, c8 = tid & 7;
                *(uint4*)&Bs[rk][c8 * 8] = *(const uint4*)&Wa[(k0 + rk) * H + c8 * 8];
            }
            __syncthreads();

            uint32_t a[2][4];
            #pragma unroll
            for (int tm = 0; tm < 2; tm++) {
                const __half* p = &As[warp_m * 32 + tm * 16 + (lane & 15)][(lane >> 4) * 8];
                uint32_t ad = (uint32_t)__cvta_generic_to_shared(p);
                asm volatile("ldmatrix.sync.aligned.m8n8.x4.shared.b16 {%0,%1,%2,%3}, [%4];"
                             : "=r"(a[tm][0]), "=r"(a[tm][1]), "=r"(a[tm][2]), "=r"(a[tm][3])
                             : "r"(ad));
            }
            #pragma unroll
            for (int np = 0; np < NP; np++) {
                uint32_t b[4];
                const __half* p = &Bs[lane & 15][warp_n * WN + np * 16 + (lane >> 4) * 8];
                uint32_t ad = (uint32_t)__cvta_generic_to_shared(p);
                asm volatile("ldmatrix.sync.aligned.m8n8.x4.trans.shared.b16 {%0,%1,%2,%3}, [%4];"
                             : "=r"(b[0]), "=r"(b[1]), "=r"(b[2]), "=r"(b[3])
                             : "r"(ad));
                #pragma unroll
                for (int tm = 0; tm < 2; tm++) {
                    asm volatile(
                        "mma.sync.aligned.m16n8k16.row.col.f32.f16.f16.f32 "
                        "{%0,%1,%2,%3}, {%4,%5,%6,%7}, {%8,%9}, {%0,%1,%2,%3};"
                        : "+f"(acc[tm][np * 2][0]), "+f"(acc[tm][np * 2][1]),
                          "+f"(acc[tm][np * 2][2]), "+f"(acc[tm][np * 2][3])
                        : "r"(a[tm][0]), "r"(a[tm][1]), "r"(a[tm][2]), "r"(a[tm][3]),
                          "r"(b[0]), "r"(b[1]));
                    asm volatile(
                        "mma.sync.aligned.m16n8k16.row.col.f32.f16.f16.f32 "
                        "{%0,%1,%2,%3}, {%4,%5,%6,%7}, {%8,%9}, {%0,%1,%2,%3};"
                        : "+f"(acc[tm][np * 2 + 1][0]), "+f"(acc[tm][np * 2 + 1][1]),
                          "+f"(acc[tm][np * 2 + 1][2]), "+f"(acc[tm][np * 2 + 1][3])
                        : "r"(a[tm][0]), "r"(a[tm][1]), "r"(a[tm][2]), "r"(a[tm][3]),
                          "r"(b[2]), "r"(b[3]));
                }
            }
            __syncthreads();
        }

        // stage-1 epilogue: unscale, bias, relu, rescale -> Mid (fp16 smem)
        #pragma unroll
        for (int tm = 0; tm < 2; tm++) {
            #pragma unroll
            for (int tn = 0; tn < NT; tn++) {
                int c = warp_n * WN + tn * 8 + tq * 2;
                float2 bb = *(const float2*)&Ba[c];
                #pragma unroll
                for (int h = 0; h < 2; h++) {
                    int rr = warp_m * 32 + tm * 16 + qid + h * 8;
                    float v0 = fmaxf(acc[tm][tn][h * 2 + 0] * SCL + bb.x, 0.0f);
                    float v1 = fmaxf(acc[tm][tn][h * 2 + 1] * SCL + bb.y, 0.0f);
                    *(__half2*)&Mid[rr][c] = __floats2half2_rn(v0 * SCLI, v1 * SCLI);
                }
            }
        }
    }
    __syncthreads();

    // ---------------- stage 2: out = relu(Mid*SCL @ Wb + bb) ----------------
    {
        float acc[2][NT][4];
        #pragma unroll
        for (int tm = 0; tm < 2; tm++)
            #pragma unroll
            for (int tn = 0; tn < NT; tn++)
                #pragma unroll
                for (int q = 0; q < 4; q++) acc[tm][tn][q] = 0.0f;

        for (int k0 = 0; k0 < H; k0 += 16) {
            // Wb tile: 16 x HOUT halfs
            if (HOUT == 128) {
                int rk = tid >> 4, c8 = tid & 15;
                *(uint4*)&Bs[rk][c8 * 8] = *(const uint4*)&Wb[(k0 + rk) * HOUT + c8 * 8];
            } else if (tid < 128) {
                int rk = tid >> 3, c8 = tid & 7;
                *(uint4*)&Bs[rk][c8 * 8] = *(const uint4*)&Wb[(k0 + rk) * HOUT + c8 * 8];
            }
            __syncthreads();

            uint32_t a[2][4];
            #pragma unroll
            for (int tm = 0; tm < 2; tm++) {
                const __half* p = &Mid[warp_m * 32 + tm * 16 + (lane & 15)]
                                      [k0 + (lane >> 4) * 8];
                uint32_t ad = (uint32_t)__cvta_generic_to_shared(p);
                asm volatile("ldmatrix.sync.aligned.m8n8.x4.shared.b16 {%0,%1,%2,%3}, [%4];"
                             : "=r"(a[tm][0]), "=r"(a[tm][1]), "=r"(a[tm][2]), "=r"(a[tm][3])
                             : "r"(ad));
            }
            #pragma unroll
            for (int np = 0; np < NP; np++) {
                uint32_t b[4];
                const __half* p = &Bs[lane & 15][warp_n * WN + np * 16 + (lane >> 4) * 8];
                uint32_t ad = (uint32_t)__cvta_generic_to_shared(p);
                asm volatile("ldmatrix.sync.aligned.m8n8.x4.trans.shared.b16 {%0,%1,%2,%3}, [%4];"
                             : "=r"(b[0]), "=r"(b[1]), "=r"(b[2]), "=r"(b[3])
                             : "r"(ad));
                #pragma unroll
                for (int tm = 0; tm < 2; tm++) {
                    asm volatile(
                        "mma.sync.aligned.m16n8k16.row.col.f32.f16.f16.f32 "
                        "{%0,%1,%2,%3}, {%4,%5,%6,%7}, {%8,%9}, {%0,%1,%2,%3};"
                        : "+f"(acc[tm][np * 2][0]), "+f"(acc[tm][np * 2][1]),
                          "+f"(acc[tm][np * 2][2]), "+f"(acc[tm][np * 2][3])
                        : "r"(a[tm][0]), "r"(a[tm][1]), "r"(a[tm][2]), "r"(a[tm][3]),
                          "r"(b[0]), "r"(b[1]));
                    asm volatile(
                        "mma.sync.aligned.m16n8k16.row.col.f32.f16.f16.f32 "
                        "{%0,%1,%2,%3}, {%4,%5,%6,%7}, {%8,%9}, {%0,%1,%2,%3};"
                        : "+f"(acc[tm][np * 2 + 1][0]), "+f"(acc[tm][np * 2 + 1][1]),
                          "+f"(acc[tm][np * 2 + 1][2]), "+f"(acc[tm][np * 2 + 1][3])
                        : "r"(a[tm][0]), "r"(a[tm][1]), "r"(a[tm][2]), "r"(a[tm][3]),
                          "r"(b[2]), "r"(b[3]));
                }
            }
            __syncthreads();
        }

        // stage-2 epilogue: unscale, bias, relu; store layer output
        #pragma unroll
        for (int tm = 0; tm < 2; tm++) {
            #pragma unroll
            for (int tn = 0; tn < NT; tn++) {
                int c = warp_n * WN + tn * 8 + tq * 2;
                float2 bb = *(const float2*)&Bb[c];
                #pragma unroll
                for (int h = 0; h < 2; h++) {
                    int r = row0 + warp_m * 32 + tm * 16 + qid + h * 8;
                    if (r < NN) {
                        float v0 = fmaxf(acc[tm][tn][h * 2 + 0] * SCL + bb.x, 0.0f);
                        float v1 = fmaxf(acc[tm][tn][h * 2 + 1] * SCL + bb.y, 0.0f);
                        if (HALF_OUT) {
                            *(__half2*)&g_xh[r * HOUT + c] = __floats2half2_rn(v0, v1);
                        } else {
                            *(float2*)&g_x[r * HOUT + c] = make_float2(v0, v1);
                        }
                    }
                }
            }
        }
    }
}

// ---------------- final FC (N,64)@(64,8)+b and emb copy ----------------
__global__ void k_fc(const float* __restrict__ W,
                     const float* __restrict__ B,
                     float* __restrict__ out,
                     float* __restrict__ emb) {
    int gw = (blockIdx.x * blockDim.x + threadIdx.x) >> 5;
    if (gw >= NN) return;
    int lane = threadIdx.x & 31;
    float v0 = g_x[gw * 64 + lane];
    float v1 = g_x[gw * 64 + 32 + lane];
    emb[gw * 64 + lane] = v0;
    emb[gw * 64 + 32 + lane] = v1;
    #pragma unroll
    for (int j = 0; j < 8; j++) {
        float p = v0 * W[lane * 8 + j] + v1 * W[(lane + 32) * 8 + j];
        #pragma unroll
        for (int o = 16; o > 0; o >>= 1)
            p += __shfl_down_sync(0xffffffffu, p, o);
        if (lane == 0) out[gw * 8 + j] = p + B[j];
    }
}

// ---------------- launch ----------------
extern "C" void kernel_launch(void* const* d_in, const int* in_sizes, int n_in,
                              void* d_out, int out_size) {
    const float* x    = (const float*)d_in[0];
    const void*  ei   = d_in[1];
    const float* eps1 = (const float*)d_in[2];
    const float* eps2 = (const float*)d_in[3];
    const float* eps3 = (const float*)d_in[4];
    const float* W1a  = (const float*)d_in[5];
    const float* b1a  = (const float*)d_in[6];
    const float* W1b  = (const float*)d_in[7];
    const float* b1b  = (const float*)d_in[8];
    const float* W2a  = (const float*)d_in[9];
    const float* b2a  = (const float*)d_in[10];
    const float* W2b  = (const float*)d_in[11];
    const float* b2b  = (const float*)d_in[12];
    const float* W3a  = (const float*)d_in[13];
    const float* b3a  = (const float*)d_in[14];
    const float* W3b  = (const float*)d_in[15];
    const float* b3b  = (const float*)d_in[16];
    const float* Wfc  = (const float*)d_in[17];
    const float* bfc  = (const float*)d_in[18];

    float* out = (float*)d_out;             // (N, 8)
    float* emb = out + NN * 8;              // (N, 64)

    // CSR build
    k_detect<<<1, 1024>>>((const long long*)ei);
    k_zero_deg<<<(NN + 255) / 256, 256>>>();
    k_hist<<<(EE + 255) / 256, 256>>>(ei);
    k_block_sums<<<SCAN_NB, SCAN_BLK>>>();
    k_scan_parts<<<1, 128>>>();
    k_scan_final<<<SCAN_NB, SCAN_BLK>>>();
    k_fill<<<(EE + 255) / 256, 256>>>(ei);

    // fp16 conversions
    k_x2h<<<(NN * 32 + 255) / 256, 256>>>(x);
    k_w2h<<<(69632 + 255) / 256, 256>>>(W1a, W1b, W2a, W2b, W3a, W3b);

    const int aggBlocks = (NN * 32 + 255) / 256;
    const int gemmBlocks = (NN + 127) / 128;

    // Weight offsets in g_wh: W1a=0 W1b=8192 W2a=24576 W2b=40960 W3a=57344 W3b=65536
    // Scaling: g_ha holds value/SCL; mid lives in smem as value/SCL; g_xh, g_x true values.

    // Layer 1: 64 -> 128 -> 128
    k_aggh<64><<<aggBlocks, 256>>>(eps1);
    k_mlp<64, 128, 128, 0, 8192, true><<<gemmBlocks, 256>>>(b1a, b1b);

    // Layer 2: 128 -> 128 -> 128
    k_aggh<128><<<aggBlocks, 256>>>(eps2);
    k_mlp<128, 128, 128, 24576, 40960, true><<<gemmBlocks, 256>>>(b2a, b2b);

    // Layer 3: 128 -> 64 -> 64 (fp32 out to g_x)
    k_aggh<128><<<aggBlocks, 256>>>(eps3);
    k_mlp<128, 64, 64, 57344, 65536, false><<<gemmBlocks, 256>>>(b3a, b3b);

    // FC + emb
    k_fc<<<aggBlocks, 256>>>(Wfc, bfc, out, emb);
}